// round 1
// baseline (speedup 1.0000x reference)
#include <cuda_runtime.h>

// DenseQConv1D analytic collapse:
//   out[b,c,l] = cos(theta[c,0]) * (S_even - S_odd) / max(S_total, 1e-24)
//   with S_* = windowed sums of a[b,l] = sum_cin x[b,cin,l]^2 over the 8-tap window.
// Derivation: out = s^T (E R) S (E R)^T s ; R S R^T = H(theta0) (x) I^8 ;
// E is a CNOT-ring permutation, linear over GF(2); conjugation leaves M_c
// 2-sparse per row (diag + p^255), and p^255 >= 128 falls outside the 128-dim
// patch support -> only +/-cos(theta[c,0]) on the diagonal, sign = (-1)^(j&1).

#define BB 8
#define C_IN 16
#define C_OUT 16
#define LL 1024
#define KK 8
#define L_OUT (LL - KK + 1)   // 1017
#define TL 128                // threads / l-positions per block
#define NQ 9

__global__ __launch_bounds__(TL) void DenseQConv1D_84542136255139_kernel(
    const float* __restrict__ x,      // [B, C_IN, L]
    const float* __restrict__ theta,  // [C_OUT, NQ]
    float* __restrict__ out)          // [B, C_OUT, L_OUT]
{
    __shared__ float a[TL + KK];      // channel-reduced squares, with halo
    __shared__ float cosv[C_OUT];

    const int b   = blockIdx.y;
    const int l0  = blockIdx.x * TL;
    const int tid = threadIdx.x;

    if (tid < C_OUT) cosv[tid] = cosf(theta[tid * NQ]);

    // a[i] = sum_c x[b, c, l0+i]^2 for i in [0, TL+7)
    for (int i = tid; i < TL + KK - 1; i += TL) {
        const int l = l0 + i;
        float s = 0.0f;
        if (l < LL) {
            const float* xb = x + (size_t)b * (C_IN * LL) + l;
            #pragma unroll
            for (int c = 0; c < C_IN; ++c) {
                float v = xb[c * LL];
                s = fmaf(v, v, s);
            }
        }
        a[i] = s;
    }
    __syncthreads();

    const int l = l0 + tid;
    if (l < L_OUT) {
        float se = a[tid]     + a[tid + 2] + a[tid + 4] + a[tid + 6];
        float so = a[tid + 1] + a[tid + 3] + a[tid + 5] + a[tid + 7];
        float tot = se + so;
        float r = (se - so) / fmaxf(tot, 1e-24f);
        float* ob = out + (size_t)b * (C_OUT * L_OUT) + l;
        #pragma unroll
        for (int c = 0; c < C_OUT; ++c) {
            ob[c * L_OUT] = cosv[c] * r;
        }
    }
}

extern "C" void kernel_launch(void* const* d_in, const int* in_sizes, int n_in,
                              void* d_out, int out_size)
{
    // Resolve inputs by element count (robust to metadata ordering):
    //   x: B*C_IN*L = 131072, theta: C_OUT*NQ = 144, entangle: 512*512 = 262144 (unused)
    const float* x = nullptr;
    const float* theta = nullptr;
    for (int i = 0; i < n_in; ++i) {
        if (in_sizes[i] == BB * C_IN * LL)      x     = (const float*)d_in[i];
        else if (in_sizes[i] == C_OUT * NQ)     theta = (const float*)d_in[i];
    }

    dim3 grid((L_OUT + TL - 1) / TL, BB);
    DenseQConv1D_84542136255139_kernel<<<grid, TL>>>(x, theta, (float*)d_out);
}

// round 2
// speedup vs baseline: 1.0048x; 1.0048x over previous
#include <cuda_runtime.h>

// DenseQConv1D analytic collapse (exact):
//   out[b,c,l] = cos(theta[c,0]) * (S_even - S_odd) / max(S_total, 1e-24)
//   with S_* = windowed sums over the 8-tap window of a[b,l] = sum_cin x[b,cin,l]^2.
// Derivation: out = s^T (E R) S (E R)^T s ; R S R^T = H(theta0) (x) I^8 ;
// E = CNOT-ring permutation (linear over GF(2)); conjugated M_c is diag +/-cos(theta[c,0])
// on the 128-dim patch support, sign = (-1)^(j&1) of tap index j.
//
// R1: latency-bound tuning — 128 CTAs (fill 148 SMs), LDG.128 x-loads, fast divide.

#define BB 8
#define C_IN 16
#define C_OUT 16
#define LL 1024
#define KK 8
#define L_OUT (LL - KK + 1)   // 1017
#define TL 64                 // l-positions per block
#define NSLOT 18              // float4 slots covering TL + 7 halo (72 floats)
#define NQ 9

__global__ __launch_bounds__(TL) void DenseQConv1D_84542136255139_kernel(
    const float* __restrict__ x,      // [B, C_IN, L]
    const float* __restrict__ theta,  // [C_OUT, NQ]
    float* __restrict__ out)          // [B, C_OUT, L_OUT]
{
    __shared__ float a[NSLOT * 4];    // channel-reduced squares (72 slots incl. halo)
    __shared__ float cosv[C_OUT];

    const int b   = blockIdx.y;
    const int l0  = blockIdx.x * TL;
    const int tid = threadIdx.x;

    if (tid < C_OUT) cosv[tid] = cosf(theta[tid * NQ]);

    // Phase 1: a[4s..4s+3] = sum_c x[b, c, l0+4s .. +3]^2, one float4 slot per thread.
    if (tid < NSLOT) {
        const int lbase = l0 + tid * 4;
        float s0 = 0.f, s1 = 0.f, s2 = 0.f, s3 = 0.f;
        if (lbase + 3 < LL) {
            const float4* xb = (const float4*)(x + (size_t)b * (C_IN * LL) + lbase);
            #pragma unroll
            for (int c = 0; c < C_IN; ++c) {
                float4 v = xb[c * (LL / 4)];
                s0 = fmaf(v.x, v.x, s0);
                s1 = fmaf(v.y, v.y, s1);
                s2 = fmaf(v.z, v.z, s2);
                s3 = fmaf(v.w, v.w, s3);
            }
        }
        // (fully OOB slots stay 0; partial slots never occur since LL % 4 == 0
        //  and the only OOB case is lbase >= LL at the last tile)
        a[tid * 4 + 0] = s0;
        a[tid * 4 + 1] = s1;
        a[tid * 4 + 2] = s2;
        a[tid * 4 + 3] = s3;
    }
    __syncthreads();

    // Phase 2: 8-tap alternating / total window sums, then 16 channel stores.
    const int l = l0 + tid;
    if (l < L_OUT) {
        float se = a[tid]     + a[tid + 2] + a[tid + 4] + a[tid + 6];
        float so = a[tid + 1] + a[tid + 3] + a[tid + 5] + a[tid + 7];
        float tot = se + so;
        float r = __fdividef(se - so, fmaxf(tot, 1e-24f));
        float* ob = out + (size_t)b * (C_OUT * L_OUT) + l;
        #pragma unroll
        for (int c = 0; c < C_OUT; ++c) {
            ob[c * L_OUT] = cosv[c] * r;
        }
    }
}

extern "C" void kernel_launch(void* const* d_in, const int* in_sizes, int n_in,
                              void* d_out, int out_size)
{
    // Resolve inputs by element count (robust to metadata ordering):
    //   x: 131072, theta: 144, entangle: 262144 (unused)
    const float* x = nullptr;
    const float* theta = nullptr;
    for (int i = 0; i < n_in; ++i) {
        if (in_sizes[i] == BB * C_IN * LL)      x     = (const float*)d_in[i];
        else if (in_sizes[i] == C_OUT * NQ)     theta = (const float*)d_in[i];
    }

    dim3 grid((L_OUT + TL - 1) / TL, BB);   // 16 x 8 = 128 CTAs (~148 SMs)
    DenseQConv1D_84542136255139_kernel<<<grid, TL>>>(x, theta, (float*)d_out);
}